// round 17
// baseline (speedup 1.0000x reference)
#include <cuda_runtime.h>
#include <math.h>

#define PH 7
#define PW 7
#define C  256
#define C4 (C / 4)
#define MAXN 1024

// Scratch (device globals; no allocation allowed)
__device__ float4 g_scoord[MAXN];  // per-sorted-roi (ybase, ystep, xbase, xstep) in feature coords
__device__ int    g_slvl[MAXN];    // sorted levels

// ---------------------------------------------------------------------------
// Kernel 1: per-roi level + coordinate bases, stable counting sort.
// Level via EXACT threshold compares instead of logf (the old version burned
// ~2us of MUFU time on one SM):
//   lvl = round_half_even(log2(sqrt(hw)) - 5) clipped to [0,3]
//   boundaries: lf=0.5 -> hw=2^11 (0.5 rounds DOWN  -> strict >)
//               lf=1.5 -> hw=2^13 (1.5 rounds UP    -> >=)
//               lf=2.5 -> hw=2^15 (2.5 rounds DOWN  -> strict >)
// Packed 4x16-bit counters in uint64; warp-shuffle inclusive scan + warp-total
// combine. Single block, 1024 threads, N <= 1024.
// ---------------------------------------------------------------------------
__global__ void level_sort_kernel(const float* __restrict__ rois, int N) {
    __shared__ unsigned long long warp_tot[32];
    int i    = threadIdx.x;
    int lane = i & 31;
    int wid  = i >> 5;

    int lvl = 0;
    float4 cb = make_float4(0.f, 0.f, 0.f, 0.f);
    unsigned long long v = 0ULL;

    if (i < N) {
        float4 rb = __ldg((const float4*)rois + i);   // y1, x1, y2, x2
        float h = rb.z - rb.x;
        float w = rb.w - rb.y;
        float hw = h * w;
        int l = (hw > 2048.0f) + (hw >= 8192.0f) + (hw > 32768.0f);
        lvl = l;
        const float inv = 1.0f / 1024.0f;
        float ny1 = rb.x * inv, nx1 = rb.y * inv, ny2 = rb.z * inv, nx2 = rb.w * inv;
        float Hm1 = (float)((256 >> l) - 1);
        float Wm1 = Hm1;
        cb.x = ny1 * Hm1;                              // ybase
        cb.y = (ny2 - ny1) * Hm1 * (1.0f / (PH - 1));  // ystep
        cb.z = nx1 * Wm1;                              // xbase
        cb.w = (nx2 - nx1) * Wm1 * (1.0f / (PW - 1));  // xstep
        v = 1ULL << (16 * lvl);
    }

    // warp inclusive scan (64-bit)
    unsigned long long incl = v;
#pragma unroll
    for (int off = 1; off < 32; off <<= 1) {
        unsigned long long t = __shfl_up_sync(0xFFFFFFFFu, incl, off);
        if (lane >= off) incl += t;
    }
    if (lane == 31) warp_tot[wid] = incl;
    __syncthreads();

    if (wid == 0) {
        unsigned long long wt = warp_tot[lane];
#pragma unroll
        for (int off = 1; off < 32; off <<= 1) {
            unsigned long long t = __shfl_up_sync(0xFFFFFFFFu, wt, off);
            if (lane >= off) wt += t;
        }
        warp_tot[lane] = wt;
    }
    __syncthreads();

    unsigned long long total = warp_tot[31];
    unsigned long long offset = (wid > 0) ? warp_tot[wid - 1] : 0ULL;
    incl += offset;

    if (i < N) {
        int rank = (int)((incl >> (16 * lvl)) & 0xFFFFULL) - 1;
        int base = 0;
#pragma unroll
        for (int l = 0; l < 4; l++)
            if (l < lvl) base += (int)((total >> (16 * l)) & 0xFFFFULL);
        int pos = base + rank;
        g_slvl[pos] = lvl;
        g_scoord[pos] = cb;
    }
}

// ---------------------------------------------------------------------------
// Kernel 2: bilinear gather, split-burst float4 (unchanged from best: 16.5us).
// grid = (PH, N); block = 64 (thread = channel-group of 4).
// Burst A: 4 px x 4 corners = 16 LDG.128 in flight, compute + store;
// Burst B: 3 px x 4 = 12 LDG.128, compute + store.  launch_bounds(64,12).
// ---------------------------------------------------------------------------
__global__ void __launch_bounds__(64, 12)
roi_align_kernel(const float* __restrict__ f0,
                 const float* __restrict__ f1,
                 const float* __restrict__ f2,
                 const float* __restrict__ f3,
                 float* __restrict__ out) {
    int py  = blockIdx.x;
    int roi = blockIdx.y;
    int c4  = threadIdx.x;   // 0..63

    float4 cb = g_scoord[roi];
    int lvl = g_slvl[roi];

    const float* f = (lvl == 0) ? f0 : (lvl == 1) ? f1 : (lvl == 2) ? f2 : f3;
    int W = 256 >> lvl;
    float Wm1 = (float)(W - 1);

    float iy = cb.x + (float)py * cb.y;
    float y0f = floorf(iy);
    float ly = iy - y0f;
    int y0 = min(max((int)y0f, 0), W - 1);
    int y1 = min(max((int)y0f + 1, 0), W - 1);
    bool vy = (iy >= 0.0f) && (iy <= Wm1);
    float omly = 1.0f - ly;

    const float4* f4p = (const float4*)f;
    const float4* row0 = f4p + (size_t)y0 * W * C4 + c4;
    const float4* row1 = f4p + (size_t)y1 * W * C4 + c4;
    float4* o = (float4*)out + ((size_t)(roi * PH + py) * PW) * C4 + c4;

    // ---------------- Burst A: px 0..3 ----------------
    {
        float4 fa[4][4];
#pragma unroll
        for (int px = 0; px < 4; px++) {
            float ix = cb.z + (float)px * cb.w;
            float x0f = floorf(ix);
            int x0 = min(max((int)x0f, 0), W - 1);
            int x1 = min(max((int)x0f + 1, 0), W - 1);
            fa[px][0] = __ldg(row0 + x0 * C4);
            fa[px][1] = __ldg(row0 + x1 * C4);
            fa[px][2] = __ldg(row1 + x0 * C4);
            fa[px][3] = __ldg(row1 + x1 * C4);
        }
#pragma unroll
        for (int px = 0; px < 4; px++) {
            float ix = cb.z + (float)px * cb.w;
            float x0f = floorf(ix);
            float lx = ix - x0f;
            bool vx = (ix >= 0.0f) && (ix <= Wm1);
            float omlx = 1.0f - lx;
            float w00 = omlx * omly;
            float w01 = lx * omly;
            float w10 = omlx * ly;
            float w11 = lx * ly;
            float4 r;
            r.x = fmaf(fa[px][3].x, w11, fmaf(fa[px][2].x, w10, fmaf(fa[px][1].x, w01, fa[px][0].x * w00)));
            r.y = fmaf(fa[px][3].y, w11, fmaf(fa[px][2].y, w10, fmaf(fa[px][1].y, w01, fa[px][0].y * w00)));
            r.z = fmaf(fa[px][3].z, w11, fmaf(fa[px][2].z, w10, fmaf(fa[px][1].z, w01, fa[px][0].z * w00)));
            r.w = fmaf(fa[px][3].w, w11, fmaf(fa[px][2].w, w10, fmaf(fa[px][1].w, w01, fa[px][0].w * w00)));
            if (!(vy && vx)) r = make_float4(0.f, 0.f, 0.f, 0.f);
            __stcs(o + px * C4, r);
        }
    }

    // ---------------- Burst B: px 4..6 ----------------
    {
        float4 fb_[3][4];
#pragma unroll
        for (int k = 0; k < 3; k++) {
            int px = 4 + k;
            float ix = cb.z + (float)px * cb.w;
            float x0f = floorf(ix);
            int x0 = min(max((int)x0f, 0), W - 1);
            int x1 = min(max((int)x0f + 1, 0), W - 1);
            fb_[k][0] = __ldg(row0 + x0 * C4);
            fb_[k][1] = __ldg(row0 + x1 * C4);
            fb_[k][2] = __ldg(row1 + x0 * C4);
            fb_[k][3] = __ldg(row1 + x1 * C4);
        }
#pragma unroll
        for (int k = 0; k < 3; k++) {
            int px = 4 + k;
            float ix = cb.z + (float)px * cb.w;
            float x0f = floorf(ix);
            float lx = ix - x0f;
            bool vx = (ix >= 0.0f) && (ix <= Wm1);
            float omlx = 1.0f - lx;
            float w00 = omlx * omly;
            float w01 = lx * omly;
            float w10 = omlx * ly;
            float w11 = lx * ly;
            float4 r;
            r.x = fmaf(fb_[k][3].x, w11, fmaf(fb_[k][2].x, w10, fmaf(fb_[k][1].x, w01, fb_[k][0].x * w00)));
            r.y = fmaf(fb_[k][3].y, w11, fmaf(fb_[k][2].y, w10, fmaf(fb_[k][1].y, w01, fb_[k][0].y * w00)));
            r.z = fmaf(fb_[k][3].z, w11, fmaf(fb_[k][2].z, w10, fmaf(fb_[k][1].z, w01, fb_[k][0].z * w00)));
            r.w = fmaf(fb_[k][3].w, w11, fmaf(fb_[k][2].w, w10, fmaf(fb_[k][1].w, w01, fb_[k][0].w * w00)));
            if (!(vy && vx)) r = make_float4(0.f, 0.f, 0.f, 0.f);
            __stcs(o + px * C4, r);
        }
    }
}

extern "C" void kernel_launch(void* const* d_in, const int* in_sizes, int n_in,
                              void* d_out, int out_size) {
    const float* f0   = (const float*)d_in[0];
    const float* f1   = (const float*)d_in[1];
    const float* f2   = (const float*)d_in[2];
    const float* f3   = (const float*)d_in[3];
    const float* rois = (const float*)d_in[4];
    float* out = (float*)d_out;

    int N = in_sizes[4] / 4;
    if (N > MAXN) N = MAXN;

    level_sort_kernel<<<1, 1024>>>(rois, N);

    dim3 grid(PH, N);
    roi_align_kernel<<<grid, 64>>>(f0, f1, f2, f3, out);
}